// round 8
// baseline (speedup 1.0000x reference)
#include <cuda_runtime.h>
#include <cuda_fp16.h>
#include <cstdint>

// GRU fused kernel v5: B=16, T=60, S=2000, C=64, H=64.
// Warp-PAIR design: two warps share 16 sequence rows; each warp owns 32 of
// the 64 gate-columns (for all of r/z/n). Halves accumulator registers
// (128 -> 64 f32) so launch_bounds(256,2) holds regs <= 128 and the SM runs
// 16 warps (2 CTAs x 8) instead of 8 -> cross-warp phase overlap of the
// tensor / smem-crossbar / MUFU pipes that were each idling >45%.
// Per-step pair h-exchange through smem: 8 STS + bar + 4 ldsm4 + bar, with
// the independent x-GEMM scheduled inside the exchange window.
// Activations use paired rcp (1 MUFU.RCP per 2 divisions): exact to ~1e-7.

namespace {

constexpr int kT = 60, kS = 2000, kC = 64, kH = 64, kG = 192;
constexpr int PITCH = 72;      // fp16 elems per smem row (144B) -> conflict-free ldsm
constexpr int THREADS = 256;   // 8 warps = 4 pairs = 64 rows per CTA
constexpr int NROWS = 16 * 2000;

constexpr int OFF_WIH = 0;
constexpr int OFF_WHH = OFF_WIH + kG * PITCH * 2;   // 27648
constexpr int OFF_BRZ = OFF_WHH + kG * PITCH * 2;   // 55296  f32[128]
constexpr int OFF_BIN = OFF_BRZ + 128 * 4;          // f32[64]
constexpr int OFF_BHN = OFF_BIN + 64 * 4;           // f32[64]
constexpr int OFF_HX = OFF_BHN + 64 * 4;            // 4 pair buffers
constexpr int HX_PAIR = 16 * PITCH * 2;             // 2304 B
constexpr int SMEM_BYTES = OFF_HX + 4 * HX_PAIR;    // 65536 B -> 2 CTAs/SM

__device__ __forceinline__ uint32_t smem_u32(const void* p) {
  return (uint32_t)__cvta_generic_to_shared(p);
}

__device__ __forceinline__ void ldsm4(uint32_t r[4], uint32_t addr) {
  asm volatile("ldmatrix.sync.aligned.m8n8.x4.shared.b16 {%0,%1,%2,%3}, [%4];\n"
               : "=r"(r[0]), "=r"(r[1]), "=r"(r[2]), "=r"(r[3]) : "r"(addr));
}

__device__ __forceinline__ void mma16816(float d[4], const uint32_t a[4],
                                         const uint32_t b0, const uint32_t b1) {
  asm volatile(
      "mma.sync.aligned.m16n8k16.row.col.f32.f16.f16.f32 "
      "{%0,%1,%2,%3},{%4,%5,%6,%7},{%8,%9},{%0,%1,%2,%3};\n"
      : "+f"(d[0]), "+f"(d[1]), "+f"(d[2]), "+f"(d[3])
      : "r"(a[0]), "r"(a[1]), "r"(a[2]), "r"(a[3]), "r"(b0), "r"(b1));
}

__device__ __forceinline__ uint32_t pack_f16x2(float a, float b) {
  __half2 h = __floats2half2_rn(a, b);
  return *reinterpret_cast<uint32_t*>(&h);
}

__device__ __forceinline__ float frcp_fast(float x) {
  float r;
  asm("rcp.approx.f32 %0, %1;" : "=f"(r) : "f"(x));
  return r;
}

}  // namespace

__global__ void __launch_bounds__(THREADS, 2)
gru_fused_kernel(const float* __restrict__ chars,
                 const float* __restrict__ Wih,
                 const float* __restrict__ Whh,
                 const float* __restrict__ bih,
                 const float* __restrict__ bhh,
                 float* __restrict__ out) {
  extern __shared__ char smem[];
  __half* wih_s = reinterpret_cast<__half*>(smem + OFF_WIH);
  __half* whh_s = reinterpret_cast<__half*>(smem + OFF_WHH);
  float* brz = reinterpret_cast<float*>(smem + OFF_BRZ);
  float* bin_s = reinterpret_cast<float*>(smem + OFF_BIN);
  float* bhn_s = reinterpret_cast<float*>(smem + OFF_BHN);

  const int tid = threadIdx.x;
  const int lane = tid & 31;
  const int wid = tid >> 5;
  const int pair = wid >> 1;       // 0..3
  const int q = wid & 1;           // column half: cols 32q..32q+31 of each gate
  const int barid = pair + 1;      // named barrier per pair (64 threads)

  // ---- one-time init: fp16 weights (padded pitch), biases ----
  for (int i = tid; i < kG * kC; i += THREADS) {
    const int g = i >> 6, c = i & 63;
    wih_s[g * PITCH + c] = __float2half_rn(Wih[i]);
    whh_s[g * PITCH + c] = __float2half_rn(Whh[i]);
  }
  if (tid < 128) brz[tid] = bih[tid] + bhh[tid];
  if (tid < 64) {
    bin_s[tid] = bih[128 + tid];
    bhn_s[tid] = bhh[128 + tid];
  }
  __syncthreads();  // the only block-wide barrier

  // ---- per-pair geometry: 16 rows shared by the two warps ----
  const int pr0 = blockIdx.x * 64 + pair * 16;
  const int bb = pr0 / kS;
  const int ss = pr0 - bb * kS;
  const int lr = lane >> 2;          // 0..7
  const int c0 = (lane & 3) * 2;     // 0,2,4,6

  const float* pxa = chars + ((size_t)bb * kT * kS + (ss + lr)) * (size_t)kC;
  const float* pxb = pxa + 8 * kC;
  const size_t tstride = (size_t)kS * kC;

  // B-fragment ldsm addressing (16 weight rows per unit)
  const int sel = lane >> 3;
  const int b_lane_off = ((lane & 7) + 8 * (sel >> 1)) * (PITCH * 2) + (sel & 1) * 16;
  const uint32_t wih_b = smem_u32(wih_s) + b_lane_off + q * 32 * (PITCH * 2);
  const uint32_t whh_b = smem_u32(whh_s) + b_lane_off + q * 32 * (PITCH * 2);

  // h exchange buffer for this pair
  __half* hx = reinterpret_cast<__half*>(smem + OFF_HX + pair * HX_PAIR);
  __half* hx_st_a = hx + lr * PITCH + 32 * q + c0;        // row lr
  __half* hx_st_b = hx + (lr + 8) * PITCH + 32 * q + c0;  // row lr+8
  const uint32_t hx_ld =
      smem_u32(hx) + (lane & 15) * (PITCH * 2) + ((lane >> 4) << 4);

  // h state: this warp's 32 cols as 4 n8 tiles, f32 C-fragment layout
  float hf[4][4];
#pragma unroll
  for (int j = 0; j < 4; ++j)
#pragma unroll
    for (int e = 0; e < 4; ++e) hf[j][e] = 0.0f;

  for (int t = 0; t < kT; ++t) {
    // ---- accumulators, bias-initialized (rows lr and lr+8 share col bias) ----
    float accR[4][4], accZ[4][4], accN[4][4], accHN[4][4];
#pragma unroll
    for (int j = 0; j < 4; ++j) {
      const int col = 32 * q + 8 * j + c0;
      const float2 bR = *reinterpret_cast<const float2*>(brz + col);
      const float2 bZ = *reinterpret_cast<const float2*>(brz + 64 + col);
      const float2 bN = *reinterpret_cast<const float2*>(bin_s + col);
      const float2 bHN = *reinterpret_cast<const float2*>(bhn_s + col);
      accR[j][0] = bR.x; accR[j][1] = bR.y; accR[j][2] = bR.x; accR[j][3] = bR.y;
      accZ[j][0] = bZ.x; accZ[j][1] = bZ.y; accZ[j][2] = bZ.x; accZ[j][3] = bZ.y;
      accN[j][0] = bN.x; accN[j][1] = bN.y; accN[j][2] = bN.x; accN[j][3] = bN.y;
      accHN[j][0] = bHN.x; accHN[j][1] = bHN.y; accHN[j][2] = bHN.x; accHN[j][3] = bHN.y;
    }

    // ---- publish this warp's h columns to the pair buffer ----
#pragma unroll
    for (int j = 0; j < 4; ++j) {
      *reinterpret_cast<uint32_t*>(hx_st_a + 8 * j) = pack_f16x2(hf[j][0], hf[j][1]);
      *reinterpret_cast<uint32_t*>(hx_st_b + 8 * j) = pack_f16x2(hf[j][2], hf[j][3]);
    }
    asm volatile("bar.sync %0, %1;" :: "r"(barid), "r"(64) : "memory");

    // ---- x load + pack (independent work inside the exchange window) ----
    uint32_t xa[4][4];
#pragma unroll
    for (int kk = 0; kk < 4; ++kk) {
      const float2 v0 = *reinterpret_cast<const float2*>(pxa + 16 * kk + c0);
      const float2 v1 = *reinterpret_cast<const float2*>(pxb + 16 * kk + c0);
      const float2 v2 = *reinterpret_cast<const float2*>(pxa + 16 * kk + 8 + c0);
      const float2 v3 = *reinterpret_cast<const float2*>(pxb + 16 * kk + 8 + c0);
      xa[kk][0] = pack_f16x2(v0.x, v0.y);
      xa[kk][1] = pack_f16x2(v1.x, v1.y);
      xa[kk][2] = pack_f16x2(v2.x, v2.y);
      xa[kk][3] = pack_f16x2(v3.x, v3.y);
    }
    pxa += tstride;
    pxb += tstride;

    // ---- x-path GEMM: gi = x @ Wih^T (this warp's 32 cols of r,z,n) ----
#pragma unroll
    for (int kk = 0; kk < 4; ++kk) {
      const int koff = kk * 32;
#pragma unroll
      for (int u = 0; u < 6; ++u) {
        const int gate = u >> 1, jj2 = u & 1;
        uint32_t b[4];
        ldsm4(b, wih_b + (gate * 64 + jj2 * 16) * (PITCH * 2) + koff);
        float* d0 = (gate == 0) ? accR[2 * jj2] : (gate == 1) ? accZ[2 * jj2] : accN[2 * jj2];
        float* d1 = (gate == 0) ? accR[2 * jj2 + 1] : (gate == 1) ? accZ[2 * jj2 + 1] : accN[2 * jj2 + 1];
        mma16816(d0, xa[kk], b[0], b[1]);
        mma16816(d1, xa[kk], b[2], b[3]);
      }
    }

    // ---- load full-h A-fragments from the pair buffer ----
    uint32_t ha[4][4];
#pragma unroll
    for (int kk = 0; kk < 4; ++kk) ldsm4(ha[kk], hx_ld + kk * 32);
    asm volatile("bar.sync %0, %1;" :: "r"(barid), "r"(64) : "memory");

    // ---- h-path GEMM: gh = h @ Whh^T (r, z cols + hn cols) ----
#pragma unroll
    for (int kk = 0; kk < 4; ++kk) {
      const int koff = kk * 32;
#pragma unroll
      for (int u = 0; u < 6; ++u) {
        const int gate = u >> 1, jj2 = u & 1;
        uint32_t b[4];
        ldsm4(b, whh_b + (gate * 64 + jj2 * 16) * (PITCH * 2) + koff);
        float* d0 = (gate == 0) ? accR[2 * jj2] : (gate == 1) ? accZ[2 * jj2] : accHN[2 * jj2];
        float* d1 = (gate == 0) ? accR[2 * jj2 + 1] : (gate == 1) ? accZ[2 * jj2 + 1] : accHN[2 * jj2 + 1];
        mma16816(d0, ha[kk], b[0], b[1]);
        mma16816(d1, ha[kk], b[2], b[3]);
      }
    }

    // ---- elementwise GRU update (paired reciprocals: 9 MUFU / 12) ----
#pragma unroll
    for (int j = 0; j < 4; ++j) {
#pragma unroll
      for (int half = 0; half < 2; ++half) {
        const int e0 = half * 2, e1 = e0 + 1;
        const float a0 = 1.0f + __expf(-accR[j][e0]);
        const float b0 = 1.0f + __expf(-accZ[j][e0]);
        const float a1 = 1.0f + __expf(-accR[j][e1]);
        const float b1 = 1.0f + __expf(-accZ[j][e1]);
        const float ip0 = frcp_fast(a0 * b0);
        const float ip1 = frcp_fast(a1 * b1);
        const float r0 = b0 * ip0, z0 = a0 * ip0;
        const float r1 = b1 * ip1, z1 = a1 * ip1;
        const float t0 = accN[j][e0] + r0 * accHN[j][e0];
        const float t1 = accN[j][e1] + r1 * accHN[j][e1];
        const float d0 = 1.0f + __expf(-2.0f * t0);
        const float d1 = 1.0f + __expf(-2.0f * t1);
        const float ipn = frcp_fast(d0 * d1);
        const float n0 = 2.0f * d1 * ipn - 1.0f;
        const float n1 = 2.0f * d0 * ipn - 1.0f;
        hf[j][e0] = n0 + z0 * (hf[j][e0] - n0);
        hf[j][e1] = n1 + z1 * (hf[j][e1] - n1);
      }
    }
  }

  // ---- write final h (f32 state, exact): this warp's 32 cols ----
  {
    float* poa = out + (size_t)(pr0 + lr) * kH + 32 * q;
    float* pob = out + (size_t)(pr0 + lr + 8) * kH + 32 * q;
#pragma unroll
    for (int j = 0; j < 4; ++j) {
      float2 va, vb;
      va.x = hf[j][0]; va.y = hf[j][1];
      vb.x = hf[j][2]; vb.y = hf[j][3];
      *reinterpret_cast<float2*>(poa + 8 * j + c0) = va;
      *reinterpret_cast<float2*>(pob + 8 * j + c0) = vb;
    }
  }
}

extern "C" void kernel_launch(void* const* d_in, const int* in_sizes, int n_in,
                              void* d_out, int out_size) {
  const float* chars = (const float*)d_in[0];
  const float* Wih = (const float*)d_in[1];
  const float* Whh = (const float*)d_in[2];
  const float* bih = (const float*)d_in[3];
  const float* bhh = (const float*)d_in[4];
  float* out = (float*)d_out;

  cudaFuncSetAttribute(gru_fused_kernel,
                       cudaFuncAttributeMaxDynamicSharedMemorySize, SMEM_BYTES);

  const int grid = NROWS / 64;  // 500 CTAs, 8 warps each, warp-pairs of 16 rows
  gru_fused_kernel<<<grid, THREADS, SMEM_BYTES>>>(chars, Wih, Whh, bih, bhh, out);
}

// round 11
// speedup vs baseline: 1.0363x; 1.0363x over previous
#include <cuda_runtime.h>
#include <cuda_fp16.h>
#include <cstdint>

// GRU fused kernel v6: B=16, T=60, S=2000, C=64, H=64.
// Warp-pair design (v5 base): two warps share 16 sequence rows, each owns 32
// of the 64 gate-columns for all of r/z/n; per-step h exchange via smem +
// named barriers. v6 change: Whh B-fragments are PRELOADED INTO REGISTERS
// once (96 regs, constant across all 60 steps) -> the h-path GEMM issues no
// ldsm at all, halving the smem-crossbar floor that co-limited v3/v5 and
// removing smem latency from the post-barrier critical path. Wih remains
// ldsm'd in the slack x-phase.

namespace {

constexpr int kT = 60, kS = 2000, kC = 64, kH = 64, kG = 192;
constexpr int PITCH = 72;      // fp16 elems per smem row (144B) -> conflict-free ldsm
constexpr int THREADS = 256;   // 8 warps = 4 pairs = 64 rows per CTA
constexpr int NROWS = 16 * 2000;

constexpr int OFF_WIH = 0;
constexpr int OFF_WHH = OFF_WIH + kG * PITCH * 2;   // 27648
constexpr int OFF_BRZ = OFF_WHH + kG * PITCH * 2;   // 55296  f32[128]
constexpr int OFF_BIN = OFF_BRZ + 128 * 4;          // f32[64]
constexpr int OFF_BHN = OFF_BIN + 64 * 4;           // f32[64]
constexpr int OFF_HX = OFF_BHN + 64 * 4;            // 4 pair buffers
constexpr int HX_PAIR = 16 * PITCH * 2;             // 2304 B
constexpr int SMEM_BYTES = OFF_HX + 4 * HX_PAIR;    // 65536 B

__device__ __forceinline__ uint32_t smem_u32(const void* p) {
  return (uint32_t)__cvta_generic_to_shared(p);
}

__device__ __forceinline__ void ldsm4(uint32_t r[4], uint32_t addr) {
  asm volatile("ldmatrix.sync.aligned.m8n8.x4.shared.b16 {%0,%1,%2,%3}, [%4];\n"
               : "=r"(r[0]), "=r"(r[1]), "=r"(r[2]), "=r"(r[3]) : "r"(addr));
}

__device__ __forceinline__ void mma16816(float d[4], const uint32_t a[4],
                                         const uint32_t b0, const uint32_t b1) {
  asm volatile(
      "mma.sync.aligned.m16n8k16.row.col.f32.f16.f16.f32 "
      "{%0,%1,%2,%3},{%4,%5,%6,%7},{%8,%9},{%0,%1,%2,%3};\n"
      : "+f"(d[0]), "+f"(d[1]), "+f"(d[2]), "+f"(d[3])
      : "r"(a[0]), "r"(a[1]), "r"(a[2]), "r"(a[3]), "r"(b0), "r"(b1));
}

__device__ __forceinline__ uint32_t pack_f16x2(float a, float b) {
  __half2 h = __floats2half2_rn(a, b);
  return *reinterpret_cast<uint32_t*>(&h);
}

__device__ __forceinline__ float frcp_fast(float x) {
  float r;
  asm("rcp.approx.f32 %0, %1;" : "=f"(r) : "f"(x));
  return r;
}

}  // namespace

__global__ void __launch_bounds__(THREADS, 1)
gru_fused_kernel(const float* __restrict__ chars,
                 const float* __restrict__ Wih,
                 const float* __restrict__ Whh,
                 const float* __restrict__ bih,
                 const float* __restrict__ bhh,
                 float* __restrict__ out) {
  extern __shared__ char smem[];
  __half* wih_s = reinterpret_cast<__half*>(smem + OFF_WIH);
  __half* whh_s = reinterpret_cast<__half*>(smem + OFF_WHH);
  float* brz = reinterpret_cast<float*>(smem + OFF_BRZ);
  float* bin_s = reinterpret_cast<float*>(smem + OFF_BIN);
  float* bhn_s = reinterpret_cast<float*>(smem + OFF_BHN);

  const int tid = threadIdx.x;
  const int lane = tid & 31;
  const int wid = tid >> 5;
  const int pair = wid >> 1;       // 0..3
  const int q = wid & 1;           // column half: cols 32q..32q+31 of each gate
  const int barid = pair + 1;      // named barrier per pair (64 threads)

  // ---- one-time init: fp16 weights (padded pitch), biases ----
  for (int i = tid; i < kG * kC; i += THREADS) {
    const int g = i >> 6, c = i & 63;
    wih_s[g * PITCH + c] = __float2half_rn(Wih[i]);
    whh_s[g * PITCH + c] = __float2half_rn(Whh[i]);
  }
  if (tid < 128) brz[tid] = bih[tid] + bhh[tid];
  if (tid < 64) {
    bin_s[tid] = bih[128 + tid];
    bhn_s[tid] = bhh[128 + tid];
  }
  __syncthreads();  // the only block-wide barrier

  // ---- per-pair geometry: 16 rows shared by the two warps ----
  const int pr0 = blockIdx.x * 64 + pair * 16;
  const int bb = pr0 / kS;
  const int ss = pr0 - bb * kS;
  const int lr = lane >> 2;          // 0..7
  const int c0 = (lane & 3) * 2;     // 0,2,4,6

  const float* pxa = chars + ((size_t)bb * kT * kS + (ss + lr)) * (size_t)kC;
  const float* pxb = pxa + 8 * kC;
  const size_t tstride = (size_t)kS * kC;

  // B-fragment ldsm addressing (16 weight rows per unit)
  const int sel = lane >> 3;
  const int b_lane_off = ((lane & 7) + 8 * (sel >> 1)) * (PITCH * 2) + (sel & 1) * 16;
  const uint32_t wih_b = smem_u32(wih_s) + b_lane_off + q * 32 * (PITCH * 2);
  const uint32_t whh_b = smem_u32(whh_s) + b_lane_off + q * 32 * (PITCH * 2);

  // ---- preload Whh B-fragments into registers (constant for all steps) ----
  // whhB[u][kk]: u = gate*2 + jj2 (gate 0=r,1=z,2=n; jj2 = 16-col block)
  uint32_t whhB[6][4][4];
#pragma unroll
  for (int u = 0; u < 6; ++u) {
    const int gate = u >> 1, jj2 = u & 1;
#pragma unroll
    for (int kk = 0; kk < 4; ++kk) {
      ldsm4(whhB[u][kk],
            whh_b + (gate * 64 + jj2 * 16) * (PITCH * 2) + kk * 32);
    }
  }

  // h exchange buffer for this pair
  __half* hx = reinterpret_cast<__half*>(smem + OFF_HX + pair * HX_PAIR);
  __half* hx_st_a = hx + lr * PITCH + 32 * q + c0;        // row lr
  __half* hx_st_b = hx + (lr + 8) * PITCH + 32 * q + c0;  // row lr+8
  const uint32_t hx_ld =
      smem_u32(hx) + (lane & 15) * (PITCH * 2) + ((lane >> 4) << 4);

  // h state: this warp's 32 cols as 4 n8 tiles, f32 C-fragment layout
  float hf[4][4];
#pragma unroll
  for (int j = 0; j < 4; ++j)
#pragma unroll
    for (int e = 0; e < 4; ++e) hf[j][e] = 0.0f;

  for (int t = 0; t < kT; ++t) {
    // ---- accumulators, bias-initialized (rows lr and lr+8 share col bias) ----
    float accR[4][4], accZ[4][4], accN[4][4], accHN[4][4];
#pragma unroll
    for (int j = 0; j < 4; ++j) {
      const int col = 32 * q + 8 * j + c0;
      const float2 bR = *reinterpret_cast<const float2*>(brz + col);
      const float2 bZ = *reinterpret_cast<const float2*>(brz + 64 + col);
      const float2 bN = *reinterpret_cast<const float2*>(bin_s + col);
      const float2 bHN = *reinterpret_cast<const float2*>(bhn_s + col);
      accR[j][0] = bR.x; accR[j][1] = bR.y; accR[j][2] = bR.x; accR[j][3] = bR.y;
      accZ[j][0] = bZ.x; accZ[j][1] = bZ.y; accZ[j][2] = bZ.x; accZ[j][3] = bZ.y;
      accN[j][0] = bN.x; accN[j][1] = bN.y; accN[j][2] = bN.x; accN[j][3] = bN.y;
      accHN[j][0] = bHN.x; accHN[j][1] = bHN.y; accHN[j][2] = bHN.x; accHN[j][3] = bHN.y;
    }

    // ---- publish this warp's h columns to the pair buffer ----
#pragma unroll
    for (int j = 0; j < 4; ++j) {
      *reinterpret_cast<uint32_t*>(hx_st_a + 8 * j) = pack_f16x2(hf[j][0], hf[j][1]);
      *reinterpret_cast<uint32_t*>(hx_st_b + 8 * j) = pack_f16x2(hf[j][2], hf[j][3]);
    }
    asm volatile("bar.sync %0, %1;" :: "r"(barid), "r"(64) : "memory");

    // ---- x load + pack (independent work inside the exchange window) ----
    uint32_t xa[4][4];
#pragma unroll
    for (int kk = 0; kk < 4; ++kk) {
      const float2 v0 = *reinterpret_cast<const float2*>(pxa + 16 * kk + c0);
      const float2 v1 = *reinterpret_cast<const float2*>(pxb + 16 * kk + c0);
      const float2 v2 = *reinterpret_cast<const float2*>(pxa + 16 * kk + 8 + c0);
      const float2 v3 = *reinterpret_cast<const float2*>(pxb + 16 * kk + 8 + c0);
      xa[kk][0] = pack_f16x2(v0.x, v0.y);
      xa[kk][1] = pack_f16x2(v1.x, v1.y);
      xa[kk][2] = pack_f16x2(v2.x, v2.y);
      xa[kk][3] = pack_f16x2(v3.x, v3.y);
    }
    pxa += tstride;
    pxb += tstride;

    // ---- x-path GEMM: gi = x @ Wih^T (ldsm'd; this phase has slack) ----
#pragma unroll
    for (int kk = 0; kk < 4; ++kk) {
      const int koff = kk * 32;
#pragma unroll
      for (int u = 0; u < 6; ++u) {
        const int gate = u >> 1, jj2 = u & 1;
        uint32_t b[4];
        ldsm4(b, wih_b + (gate * 64 + jj2 * 16) * (PITCH * 2) + koff);
        float* d0 = (gate == 0) ? accR[2 * jj2] : (gate == 1) ? accZ[2 * jj2] : accN[2 * jj2];
        float* d1 = (gate == 0) ? accR[2 * jj2 + 1] : (gate == 1) ? accZ[2 * jj2 + 1] : accN[2 * jj2 + 1];
        mma16816(d0, xa[kk], b[0], b[1]);
        mma16816(d1, xa[kk], b[2], b[3]);
      }
    }

    // ---- load full-h A-fragments from the pair buffer ----
    uint32_t ha[4][4];
#pragma unroll
    for (int kk = 0; kk < 4; ++kk) ldsm4(ha[kk], hx_ld + kk * 32);
    asm volatile("bar.sync %0, %1;" :: "r"(barid), "r"(64) : "memory");

    // ---- h-path GEMM: gh = h @ Whh^T — B entirely from registers ----
#pragma unroll
    for (int kk = 0; kk < 4; ++kk) {
#pragma unroll
      for (int u = 0; u < 6; ++u) {
        const int gate = u >> 1, jj2 = u & 1;
        float* d0 = (gate == 0) ? accR[2 * jj2] : (gate == 1) ? accZ[2 * jj2] : accHN[2 * jj2];
        float* d1 = (gate == 0) ? accR[2 * jj2 + 1] : (gate == 1) ? accZ[2 * jj2 + 1] : accHN[2 * jj2 + 1];
        mma16816(d0, ha[kk], whhB[u][kk][0], whhB[u][kk][1]);
        mma16816(d1, ha[kk], whhB[u][kk][2], whhB[u][kk][3]);
      }
    }

    // ---- elementwise GRU update (paired reciprocals: 9 MUFU / 12) ----
#pragma unroll
    for (int j = 0; j < 4; ++j) {
#pragma unroll
      for (int half = 0; half < 2; ++half) {
        const int e0 = half * 2, e1 = e0 + 1;
        const float a0 = 1.0f + __expf(-accR[j][e0]);
        const float b0 = 1.0f + __expf(-accZ[j][e0]);
        const float a1 = 1.0f + __expf(-accR[j][e1]);
        const float b1 = 1.0f + __expf(-accZ[j][e1]);
        const float ip0 = frcp_fast(a0 * b0);
        const float ip1 = frcp_fast(a1 * b1);
        const float r0 = b0 * ip0, z0 = a0 * ip0;
        const float r1 = b1 * ip1, z1 = a1 * ip1;
        const float t0 = accN[j][e0] + r0 * accHN[j][e0];
        const float t1 = accN[j][e1] + r1 * accHN[j][e1];
        const float d0 = 1.0f + __expf(-2.0f * t0);
        const float d1 = 1.0f + __expf(-2.0f * t1);
        const float ipn = frcp_fast(d0 * d1);
        const float n0 = 2.0f * d1 * ipn - 1.0f;
        const float n1 = 2.0f * d0 * ipn - 1.0f;
        hf[j][e0] = n0 + z0 * (hf[j][e0] - n0);
        hf[j][e1] = n1 + z1 * (hf[j][e1] - n1);
      }
    }
  }

  // ---- write final h (f32 state, exact): this warp's 32 cols ----
  {
    float* poa = out + (size_t)(pr0 + lr) * kH + 32 * q;
    float* pob = out + (size_t)(pr0 + lr + 8) * kH + 32 * q;
#pragma unroll
    for (int j = 0; j < 4; ++j) {
      float2 va, vb;
      va.x = hf[j][0]; va.y = hf[j][1];
      vb.x = hf[j][2]; vb.y = hf[j][3];
      *reinterpret_cast<float2*>(poa + 8 * j + c0) = va;
      *reinterpret_cast<float2*>(pob + 8 * j + c0) = vb;
    }
  }
}

extern "C" void kernel_launch(void* const* d_in, const int* in_sizes, int n_in,
                              void* d_out, int out_size) {
  const float* chars = (const float*)d_in[0];
  const float* Wih = (const float*)d_in[1];
  const float* Whh = (const float*)d_in[2];
  const float* bih = (const float*)d_in[3];
  const float* bhh = (const float*)d_in[4];
  float* out = (float*)d_out;

  cudaFuncSetAttribute(gru_fused_kernel,
                       cudaFuncAttributeMaxDynamicSharedMemorySize, SMEM_BYTES);

  const int grid = NROWS / 64;  // 500 CTAs, 8 warps each, warp-pairs of 16 rows
  gru_fused_kernel<<<grid, THREADS, SMEM_BYTES>>>(chars, Wih, Whh, bih, bhh, out);
}